// round 4
// baseline (speedup 1.0000x reference)
#include <cuda_runtime.h>
#include <math.h>

// Problem constants (fixed shapes for this problem)
#define NMAX 16384
#define KCB  2048
#define DDIM 512

// ---------------- device scratch (no allocations allowed) ----------------
__device__ float  g_sim[(size_t)NMAX * KCB];   // similarity matrix [N, K]
__device__ float  g_div[KCB];                  // sum over rows of softmax scores
__device__ float  g_counts[KCB];               // hard-assignment counts
__device__ int    g_nn[NMAX];                  // argmax index per row
__device__ double g_hclust;                    // sum over rows of sum_k p*log2(p+eps)
__device__ float  g_loss;                      // final scalar loss

// ---------------- f32x2 helpers (packed fp32 FMA, sm_100+) ----------------
__device__ __forceinline__ unsigned long long bcast2(float x) {
    unsigned long long r;
    asm("mov.b64 %0, {%1, %1};" : "=l"(r) : "f"(x));
    return r;
}
__device__ __forceinline__ void ffma2(unsigned long long &d,
                                      unsigned long long a,
                                      unsigned long long b) {
    asm("fma.rn.f32x2 %0, %1, %2, %0;" : "+l"(d) : "l"(a), "l"(b));
}
__device__ __forceinline__ float2 unpack2(unsigned long long v) {
    float2 r;
    asm("mov.b64 {%0, %1}, %2;" : "=f"(r.x), "=f"(r.y) : "l"(v));
    return r;
}

// ---------------- zero accumulators (replayed every graph launch) ----------
__global__ void zero_kernel(int K) {
    int t = blockIdx.x * blockDim.x + threadIdx.x;
    for (int c = t; c < K; c += blockDim.x * gridDim.x) {
        g_div[c] = 0.0f;
        g_counts[c] = 0.0f;
    }
    if (t == 0) g_hclust = 0.0;
}

// ---------------- SGEMM: g_sim = A[M,K] * B[N,K]^T  (fp32, f32x2 FMA) ------
#define BM 128
#define BN 128
#define BK 16
#define LDT 132   // BM + 4 padding: conflict-free, keeps 16B alignment

__global__ __launch_bounds__(256, 2) void gemm_kernel(
    const float* __restrict__ A, const float* __restrict__ B,
    int M, int N, int K)
{
    __shared__ __align__(16) float As[2][BK][LDT];
    __shared__ __align__(16) float Bs[2][BK][LDT];

    const int tid = threadIdx.x;
    const int bm = blockIdx.y * BM;
    const int bn = blockIdx.x * BN;

    // gmem->smem load mapping: each thread loads 2 float4 of A and 2 of B
    const int lrow0 = tid >> 2;        // 0..63
    const int lrow1 = lrow0 + 64;      // 64..127
    const int lk    = (tid & 3) << 2;  // 0,4,8,12

    const float* Ap0 = A + (size_t)(bm + lrow0) * K + lk;
    const float* Ap1 = A + (size_t)(bm + lrow1) * K + lk;
    const float* Bp0 = B + (size_t)(bn + lrow0) * K + lk;
    const float* Bp1 = B + (size_t)(bn + lrow1) * K + lk;

    // compute mapping: 8 warps = 2(m) x 4(n); lane = 8(m) x 4(n)
    const int warp = tid >> 5;
    const int lane = tid & 31;
    const int m0 = (warp & 1) * 64 + (lane >> 2) * 4;
    const int m1 = m0 + 32;
    const int n0 = (warp >> 1) * 32 + (lane & 3) * 4;
    const int n1 = n0 + 16;

    unsigned long long acc[4][8];
#pragma unroll
    for (int i = 0; i < 4; i++)
#pragma unroll
        for (int j = 0; j < 8; j++) acc[i][j] = 0ull;

    float4 ra0 = *(const float4*)Ap0;
    float4 ra1 = *(const float4*)Ap1;
    float4 rb0 = *(const float4*)Bp0;
    float4 rb1 = *(const float4*)Bp1;

    int buf = 0;
    As[0][lk+0][lrow0]=ra0.x; As[0][lk+1][lrow0]=ra0.y; As[0][lk+2][lrow0]=ra0.z; As[0][lk+3][lrow0]=ra0.w;
    As[0][lk+0][lrow1]=ra1.x; As[0][lk+1][lrow1]=ra1.y; As[0][lk+2][lrow1]=ra1.z; As[0][lk+3][lrow1]=ra1.w;
    Bs[0][lk+0][lrow0]=rb0.x; Bs[0][lk+1][lrow0]=rb0.y; Bs[0][lk+2][lrow0]=rb0.z; Bs[0][lk+3][lrow0]=rb0.w;
    Bs[0][lk+0][lrow1]=rb1.x; Bs[0][lk+1][lrow1]=rb1.y; Bs[0][lk+2][lrow1]=rb1.z; Bs[0][lk+3][lrow1]=rb1.w;
    __syncthreads();

    const int KT = K / BK;
    for (int kt = 0; kt < KT; kt++) {
        if (kt + 1 < KT) {
            int off = (kt + 1) * BK;
            ra0 = *(const float4*)(Ap0 + off);
            ra1 = *(const float4*)(Ap1 + off);
            rb0 = *(const float4*)(Bp0 + off);
            rb1 = *(const float4*)(Bp1 + off);
        }
#pragma unroll
        for (int kk = 0; kk < BK; kk++) {
            ulonglong2 av0 = *(const ulonglong2*)&As[buf][kk][m0];
            ulonglong2 av1 = *(const ulonglong2*)&As[buf][kk][m1];
            float4 bv0 = *(const float4*)&Bs[buf][kk][n0];
            float4 bv1 = *(const float4*)&Bs[buf][kk][n1];
            unsigned long long ap[4] = { av0.x, av0.y, av1.x, av1.y };
            unsigned long long bb[8];
            bb[0]=bcast2(bv0.x); bb[1]=bcast2(bv0.y); bb[2]=bcast2(bv0.z); bb[3]=bcast2(bv0.w);
            bb[4]=bcast2(bv1.x); bb[5]=bcast2(bv1.y); bb[6]=bcast2(bv1.z); bb[7]=bcast2(bv1.w);
#pragma unroll
            for (int i = 0; i < 4; i++)
#pragma unroll
                for (int j = 0; j < 8; j++) ffma2(acc[i][j], ap[i], bb[j]);
        }
        if (kt + 1 < KT) {
            int nb = buf ^ 1;
            As[nb][lk+0][lrow0]=ra0.x; As[nb][lk+1][lrow0]=ra0.y; As[nb][lk+2][lrow0]=ra0.z; As[nb][lk+3][lrow0]=ra0.w;
            As[nb][lk+0][lrow1]=ra1.x; As[nb][lk+1][lrow1]=ra1.y; As[nb][lk+2][lrow1]=ra1.z; As[nb][lk+3][lrow1]=ra1.w;
            Bs[nb][lk+0][lrow0]=rb0.x; Bs[nb][lk+1][lrow0]=rb0.y; Bs[nb][lk+2][lrow0]=rb0.z; Bs[nb][lk+3][lrow0]=rb0.w;
            Bs[nb][lk+0][lrow1]=rb1.x; Bs[nb][lk+1][lrow1]=rb1.y; Bs[nb][lk+2][lrow1]=rb1.z; Bs[nb][lk+3][lrow1]=rb1.w;
            __syncthreads();
            buf = nb;
        }
    }

    // epilogue: each acc pair holds (row m_even, row m_even+1) for one n
#pragma unroll
    for (int i = 0; i < 4; i++) {
        int mb = ((i < 2) ? m0 : m1) + (i & 1) * 2;
        float2 c0 = unpack2(acc[i][0]); float2 c1 = unpack2(acc[i][1]);
        float2 c2 = unpack2(acc[i][2]); float2 c3 = unpack2(acc[i][3]);
        float2 c4 = unpack2(acc[i][4]); float2 c5 = unpack2(acc[i][5]);
        float2 c6 = unpack2(acc[i][6]); float2 c7 = unpack2(acc[i][7]);
        float4 lo0 = make_float4(c0.x, c1.x, c2.x, c3.x);
        float4 hi0 = make_float4(c0.y, c1.y, c2.y, c3.y);
        float4 lo1 = make_float4(c4.x, c5.x, c6.x, c7.x);
        float4 hi1 = make_float4(c4.y, c5.y, c6.y, c7.y);
        size_t r0 = (size_t)(bm + mb) * N + bn;
        size_t r1 = r0 + N;
        *(float4*)&g_sim[r0 + n0] = lo0;
        *(float4*)&g_sim[r1 + n0] = hi0;
        *(float4*)&g_sim[r0 + n1] = lo1;
        *(float4*)&g_sim[r1 + n1] = hi1;
    }
}

// ---------------- softmax / argmax / entropy / diversity -------------------
// 256 threads per block, 16 rows per block, K == 2048 (8 cols per thread)
__global__ void softmax_kernel(int N, int K)
{
    __shared__ float  sdiv[KCB];
    __shared__ float  rv[256];
    __shared__ int    ri[256];
    __shared__ double dv[256];
    const int tid = threadIdx.x;

    for (int c = tid; c < K; c += 256) sdiv[c] = 0.0f;
    __syncthreads();

    double hloc = 0.0;
    const int row0 = blockIdx.x * 16;
    for (int r = 0; r < 16; r++) {
        const int row = row0 + r;
        const float* __restrict__ srow = g_sim + (size_t)row * K;

        float s[8];
#pragma unroll
        for (int j = 0; j < 8; j++) s[j] = srow[tid + 256 * j];

        // local max with first-occurrence tie-break (column order)
        float m = s[0]; int mi = tid;
#pragma unroll
        for (int j = 1; j < 8; j++) {
            int c = tid + 256 * j;
            if (s[j] > m) { m = s[j]; mi = c; }
        }
        rv[tid] = m; ri[tid] = mi;
        __syncthreads();
        for (int off = 128; off > 0; off >>= 1) {
            if (tid < off) {
                float ov = rv[tid + off]; int oi = ri[tid + off];
                if (ov > rv[tid] || (ov == rv[tid] && oi < ri[tid])) {
                    rv[tid] = ov; ri[tid] = oi;
                }
            }
            __syncthreads();
        }
        float rowmax = rv[0]; int rowidx = ri[0];
        __syncthreads();

        float e[8]; float ts = 0.0f;
#pragma unroll
        for (int j = 0; j < 8; j++) { e[j] = expf(s[j] - rowmax); ts += e[j]; }
        rv[tid] = ts;
        __syncthreads();
        for (int off = 128; off > 0; off >>= 1) {
            if (tid < off) rv[tid] += rv[tid + off];
            __syncthreads();
        }
        float dsum = rv[0];
        __syncthreads();

        float hrow = 0.0f;
#pragma unroll
        for (int j = 0; j < 8; j++) {
            float p = e[j] / dsum;
            sdiv[tid + 256 * j] += p;
            hrow += p * log2f(p + 1e-8f);
        }
        hloc += (double)hrow;

        if (tid == 0) {
            g_nn[row] = rowidx;
            atomicAdd(&g_counts[rowidx], 1.0f);
        }
    }

    __syncthreads();
    for (int c = tid; c < K; c += 256) atomicAdd(&g_div[c], sdiv[c]);

    dv[tid] = hloc;
    __syncthreads();
    for (int off = 128; off > 0; off >>= 1) {
        if (tid < off) dv[tid] += dv[tid + off];
        __syncthreads();
    }
    if (tid == 0) atomicAdd(&g_hclust, dv[0]);
}

// ---------------- loss + new_counts ----------------------------------------
__global__ void finalize_kernel(const float* __restrict__ cc,
                                const int* __restrict__ train,
                                float* __restrict__ out_counts,
                                int N, int K)
{
    __shared__ double dv[256];
    const int tid = threadIdx.x;
    const float invN = 1.0f / (float)N;
    const int tr = train[0];

    double acc = 0.0;
    for (int c = tid; c < K; c += 256) {
        float d = g_div[c] * invN;
        acc += (double)(d * log2f(d + 1e-8f));
        float nc = tr ? (0.99f * cc[c] + 0.01f * g_counts[c]) : cc[c];
        out_counts[c] = nc;
    }
    dv[tid] = acc;
    __syncthreads();
    for (int off = 128; off > 0; off >>= 1) {
        if (tid < off) dv[tid] += dv[tid + off];
        __syncthreads();
    }
    if (tid == 0) {
        float h_clust = -(float)(g_hclust / (double)N);
        float h_div   = -(float)dv[0];
        g_loss = h_clust - 1.0f /*GAMMA*/ * h_div;   // h_clust - GAMMA*h_diversity
    }
}

// ---------------- quantized output (warp per row) ---------------------------
__global__ void quantize_kernel(const float* __restrict__ inp,
                                const float* __restrict__ cb,
                                float* __restrict__ outq, int N, int D)
{
    const int warp = threadIdx.x >> 5;
    const int lane = threadIdx.x & 31;
    const int row = blockIdx.x * 8 + warp;
    if (row >= N) return;

    const int idx = g_nn[row];
    const float* __restrict__ q = cb + (size_t)idx * D;
    const float* __restrict__ x = inp + (size_t)row * D;
    float* __restrict__ o = outq + (size_t)row * D;

    float4 qa[4];
    float s = 0.0f;
#pragma unroll
    for (int j = 0; j < 4; j++) {
        qa[j] = *(const float4*)&q[(lane + 32 * j) * 4];
        s += qa[j].x + qa[j].y + qa[j].z + qa[j].w;
    }
#pragma unroll
    for (int off = 16; off > 0; off >>= 1) s += __shfl_xor_sync(0xffffffffu, s, off);
    const float mean = s / (float)D;

    float ss = 0.0f;
#pragma unroll
    for (int j = 0; j < 4; j++) {
        qa[j].x -= mean; qa[j].y -= mean; qa[j].z -= mean; qa[j].w -= mean;
        ss += qa[j].x*qa[j].x + qa[j].y*qa[j].y + qa[j].z*qa[j].z + qa[j].w*qa[j].w;
    }
#pragma unroll
    for (int off = 16; off > 0; off >>= 1) ss += __shfl_xor_sync(0xffffffffu, ss, off);
    const float nrm = sqrtf(ss);

#pragma unroll
    for (int j = 0; j < 4; j++) {
        float4 xi = *(const float4*)&x[(lane + 32 * j) * 4];
        float4 ov;
        // straight-through: inputs + (q_norm - inputs), matching reference fp32 ops
        ov.x = xi.x + (qa[j].x / nrm - xi.x);
        ov.y = xi.y + (qa[j].y / nrm - xi.y);
        ov.z = xi.z + (qa[j].z / nrm - xi.z);
        ov.w = xi.w + (qa[j].w / nrm - xi.w);
        *(float4*)&o[(lane + 32 * j) * 4] = ov;
    }
}

// ---------------- bulk output writers ---------------------------------------
__global__ void fill_loss_kernel(float* __restrict__ dst, size_t n4)
{
    const float v = g_loss;
    const float4 f = make_float4(v, v, v, v);
    size_t i = (size_t)blockIdx.x * blockDim.x + threadIdx.x;
    const size_t stride = (size_t)gridDim.x * blockDim.x;
    for (; i < n4; i += stride) ((float4*)dst)[i] = f;
}

__global__ void write_idx_kernel(float* __restrict__ dst, int N)
{
    int i = blockIdx.x * blockDim.x + threadIdx.x;
    if (i < N) dst[i] = (float)g_nn[i];
}

__global__ void copy_kernel(const float* __restrict__ src, float* __restrict__ dst, size_t n4)
{
    size_t i = (size_t)blockIdx.x * blockDim.x + threadIdx.x;
    const size_t stride = (size_t)gridDim.x * blockDim.x;
    for (; i < n4; i += stride) ((float4*)dst)[i] = ((const float4*)src)[i];
}

// ---------------- launch ----------------------------------------------------
extern "C" void kernel_launch(void* const* d_in, const int* in_sizes, int n_in,
                              void* d_out, int out_size)
{
    const float* inp = (const float*)d_in[0];
    const float* cb  = (const float*)d_in[1];
    const float* cc  = (const float*)d_in[2];
    const int*   trn = (const int*)d_in[3];

    const int K = in_sizes[2];            // 2048
    const int D = in_sizes[1] / K;        // 512
    const int N = in_sizes[0] / D;        // 16384

    float* out = (float*)d_out;
    const size_t qN    = (size_t)N * D;
    const size_t lossN = (size_t)N * K;
    float* out_q    = out;
    float* out_loss = out + qN;
    float* out_idx  = out + qN + lossN;
    float* out_cb   = out + qN + lossN + (size_t)N;
    float* out_cnt  = out + qN + lossN + (size_t)N + (size_t)K * D;

    zero_kernel<<<1, 256>>>(K);

    dim3 ggrid(K / BN, N / BM);
    gemm_kernel<<<ggrid, 256>>>(inp, cb, N, K, D);

    softmax_kernel<<<N / 16, 256>>>(N, K);
    finalize_kernel<<<1, 256>>>(cc, trn, out_cnt, N, K);

    quantize_kernel<<<N / 8, 256>>>(inp, cb, out_q, N, D);
    fill_loss_kernel<<<4096, 256>>>(out_loss, lossN / 4);
    write_idx_kernel<<<(N + 255) / 256, 256>>>(out_idx, N);
    copy_kernel<<<2048, 256>>>(cb, out_cb, (size_t)K * D / 4);
}

// round 9
// speedup vs baseline: 1.3845x; 1.3845x over previous
#include <cuda_runtime.h>
#include <cuda_fp16.h>
#include <cstdint>
#include <math.h>

// Problem constants (fixed shapes for this problem)
#define NMAX 16384
#define KCB  2048
#define DDIM 512

// ---------------- device scratch (no allocations allowed) ----------------
__device__ float  g_sim[(size_t)NMAX * KCB];   // similarity matrix [N, K]
__device__ float  g_div[KCB];
__device__ float  g_counts[KCB];
__device__ int    g_nn[NMAX];
__device__ double g_hclust;
__device__ float  g_loss;

// fp16 2-way split planes (a2 unscaled; b2 scaled by 2048)
__device__ __half g_A1[(size_t)NMAX * DDIM];
__device__ __half g_A2[(size_t)NMAX * DDIM];
__device__ __half g_B1[(size_t)KCB * DDIM];
__device__ __half g_B2[(size_t)KCB * DDIM];

// ---------------- PTX helpers ------------------------------------------------
__device__ __forceinline__ uint32_t smem_to_u32(const void* smem_ptr) {
    uint32_t addr;
    asm("{ .reg .u64 tmp; cvta.to.shared.u64 tmp, %1; cvt.u32.u64 %0, tmp; }"
        : "=r"(addr) : "l"(smem_ptr));
    return addr;
}
__device__ __forceinline__ void cp_async16(uint32_t dst, const void* src) {
    asm volatile("cp.async.cg.shared.global [%0], [%1], 16;\n"
                 :: "r"(dst), "l"(src));
}
#define CP_COMMIT() asm volatile("cp.async.commit_group;\n" ::: "memory")
#define CP_WAIT(n)  asm volatile("cp.async.wait_group %0;\n" :: "n"(n) : "memory")

__device__ __forceinline__ void ldsm_x4(uint32_t* r, uint32_t addr) {
    asm volatile("ldmatrix.sync.aligned.m8n8.x4.shared.b16 {%0,%1,%2,%3}, [%4];"
                 : "=r"(r[0]), "=r"(r[1]), "=r"(r[2]), "=r"(r[3]) : "r"(addr));
}
#define MMA16816(d, a, b) \
    asm volatile("mma.sync.aligned.m16n8k16.row.col.f32.f16.f16.f32 " \
        "{%0,%1,%2,%3}, {%4,%5,%6,%7}, {%8,%9}, {%0,%1,%2,%3};" \
        : "+f"((d)[0]), "+f"((d)[1]), "+f"((d)[2]), "+f"((d)[3]) \
        : "r"((a)[0]), "r"((a)[1]), "r"((a)[2]), "r"((a)[3]), \
          "r"((b)[0]), "r"((b)[1]))

// ---------------- zero accumulators -----------------------------------------
__global__ void zero_kernel(int K) {
    int t = blockIdx.x * blockDim.x + threadIdx.x;
    for (int c = t; c < K; c += blockDim.x * gridDim.x) {
        g_div[c] = 0.0f;
        g_counts[c] = 0.0f;
    }
    if (t == 0) g_hclust = 0.0;
}

// ---------------- fp32 -> 2x fp16 split -------------------------------------
__global__ void split_a_kernel(const float* __restrict__ x, int n4)
{
    int i = blockIdx.x * blockDim.x + threadIdx.x;
    if (i >= n4) return;
    float4 v = ((const float4*)x)[i];
    float f[4] = { v.x, v.y, v.z, v.w };
    union P { __half h[4]; uint2 u; } p1, p2;
#pragma unroll
    for (int j = 0; j < 4; j++) {
        __half a = __float2half_rn(f[j]);
        p1.h[j] = a;
        p2.h[j] = __float2half_rn(f[j] - __half2float(a));  // unscaled residual
    }
    ((uint2*)g_A1)[i] = p1.u;
    ((uint2*)g_A2)[i] = p2.u;
}
__global__ void split_b_kernel(const float* __restrict__ x, int n4)
{
    int i = blockIdx.x * blockDim.x + threadIdx.x;
    if (i >= n4) return;
    float4 v = ((const float4*)x)[i];
    float f[4] = { v.x, v.y, v.z, v.w };
    union P { __half h[4]; uint2 u; } p1, p2;
#pragma unroll
    for (int j = 0; j < 4; j++) {
        __half a = __float2half_rn(f[j]);
        p1.h[j] = a;
        p2.h[j] = __float2half_rn((f[j] - __half2float(a)) * 2048.0f);  // scaled
    }
    ((uint2*)g_B1)[i] = p1.u;
    ((uint2*)g_B2)[i] = p2.u;
}

// ---------------- HMMA GEMM: g_sim = A[M,D] * B[K,D]^T ----------------------
// CTA tile 128x128, BK=32, 2-stage cp.async pipeline, 8 warps (2M x 4N),
// warp tile 64x32. Split products: ACC0 += a1*b1 + a2*b1 ; ACC1 += a1*b2.
// NOTE: for mma row.col, B stored [n][k] (k-contiguous) loads with PLAIN
// ldmatrix (no .trans) using the exact same addressing as the A operand.
#define BMT 128
#define BNT 128
#define BKT 32
#define STAGE_B 32768           // 4 tiles x (128*32*2B)
#define TOFF_A1 0
#define TOFF_A2 8192
#define TOFF_B1 16384
#define TOFF_B2 24576
#define GEMM_SMEM (2 * STAGE_B) // 65536

__global__ __launch_bounds__(256, 1) void gemm_hmma_kernel()
{
    extern __shared__ __align__(128) char smem[];
    const uint32_t sbase = smem_to_u32(smem);
    const int tid  = threadIdx.x;
    const int lane = tid & 31;
    const int wid  = tid >> 5;
    const int bn = blockIdx.x * BNT;
    const int bm = blockIdx.y * BMT;

    const __half* gA1 = g_A1 + (size_t)bm * DDIM;
    const __half* gA2 = g_A2 + (size_t)bm * DDIM;
    const __half* gB1 = g_B1 + (size_t)bn * DDIM;
    const __half* gB2 = g_B2 + (size_t)bn * DDIM;

    // per-thread load slots: 2 x 16B per tile (512 chunks / 256 threads)
    // chunk q: row r = q>>2 (0..127), col-chunk c = q&3 (8 halfs each)
    const int q0 = tid, q1 = tid + 256;
    const int r0 = q0 >> 2, c0 = q0 & 3;
    const int r1 = q1 >> 2, c1 = q1 & 3;
    const uint32_t so0 = (uint32_t)(r0 * 64 + ((c0 ^ (r0 & 3)) << 4));
    const uint32_t so1 = (uint32_t)(r1 * 64 + ((c1 ^ (r1 & 3)) << 4));
    const size_t go0 = (size_t)r0 * DDIM + c0 * 8;
    const size_t go1 = (size_t)r1 * DDIM + c1 * 8;

    // compute mapping: warp (wm, wn), 4 m16 tiles x 4 n8 tiles
    const int wm = (wid >> 2) * 64;
    const int wn = (wid & 3) * 32;

    float acc0[4][4][4];
    float acc1[4][4][4];
#pragma unroll
    for (int i = 0; i < 4; i++)
#pragma unroll
        for (int j = 0; j < 4; j++)
#pragma unroll
            for (int k = 0; k < 4; k++) { acc0[i][j][k] = 0.0f; acc1[i][j][k] = 0.0f; }

    const int NKT = DDIM / BKT;  // 16

#define ISSUE_STAGE(kt) do { \
    uint32_t sb_ = sbase + (uint32_t)((kt) & 1) * STAGE_B; \
    size_t ko_ = (size_t)(kt) * BKT; \
    cp_async16(sb_ + TOFF_A1 + so0, gA1 + go0 + ko_); \
    cp_async16(sb_ + TOFF_A1 + so1, gA1 + go1 + ko_); \
    cp_async16(sb_ + TOFF_A2 + so0, gA2 + go0 + ko_); \
    cp_async16(sb_ + TOFF_A2 + so1, gA2 + go1 + ko_); \
    cp_async16(sb_ + TOFF_B1 + so0, gB1 + go0 + ko_); \
    cp_async16(sb_ + TOFF_B1 + so1, gB1 + go1 + ko_); \
    cp_async16(sb_ + TOFF_B2 + so0, gB2 + go0 + ko_); \
    cp_async16(sb_ + TOFF_B2 + so1, gB2 + go1 + ko_); \
} while (0)

    ISSUE_STAGE(0); CP_COMMIT();
    ISSUE_STAGE(1); CP_COMMIT();
    CP_WAIT(1);
    __syncthreads();

    // ldmatrix lane-address components (same pattern for A and B operands)
    const int f_lr = lane & 15;          // row within 16-row tile
    const int f_hi = lane >> 4;          // k-chunk select (0/1)

    for (int kt = 0; kt < NKT; kt++) {
        const uint32_t sb = sbase + (uint32_t)(kt & 1) * STAGE_B;

#pragma unroll
        for (int kc = 0; kc < 2; kc++) {
            // ---- A fragments (both planes) ----
            uint32_t a1f[4][4], a2f[4][4];
#pragma unroll
            for (int mt = 0; mt < 4; mt++) {
                int r = wm + mt * 16 + f_lr;
                int c = kc * 2 + f_hi;
                uint32_t ad = sb + (uint32_t)(r * 64 + ((c ^ (r & 3)) << 4));
                ldsm_x4(a1f[mt], ad + TOFF_A1);
                ldsm_x4(a2f[mt], ad + TOFF_A2);
            }
            // ---- B fragments (both planes), PLAIN ldmatrix on [n][k] tile ----
            uint32_t b1f[4][2], b2f[4][2];
#pragma unroll
            for (int nt2 = 0; nt2 < 2; nt2++) {
                int r = wn + nt2 * 16 + f_lr;
                int c = kc * 2 + f_hi;
                uint32_t bd = sb + (uint32_t)(r * 64 + ((c ^ (r & 3)) << 4));
                uint32_t m[4];
                ldsm_x4(m, bd + TOFF_B1);
                // m0 = {k0-7, n0-7}, m1 = {k0-7, n8-15},
                // m2 = {k8-15, n0-7}, m3 = {k8-15, n8-15}
                b1f[nt2*2+0][0] = m[0]; b1f[nt2*2+0][1] = m[2];
                b1f[nt2*2+1][0] = m[1]; b1f[nt2*2+1][1] = m[3];
                ldsm_x4(m, bd + TOFF_B2);
                b2f[nt2*2+0][0] = m[0]; b2f[nt2*2+0][1] = m[2];
                b2f[nt2*2+1][0] = m[1]; b2f[nt2*2+1][1] = m[3];
            }
            // ---- 48 mma: a1*b1 + a2*b1 -> ACC0 ; a1*b2 -> ACC1 ----
#pragma unroll
            for (int mt = 0; mt < 4; mt++)
#pragma unroll
                for (int nt = 0; nt < 4; nt++) {
                    MMA16816(acc0[mt][nt], a1f[mt], b1f[nt]);
                    MMA16816(acc0[mt][nt], a2f[mt], b1f[nt]);
                    MMA16816(acc1[mt][nt], a1f[mt], b2f[nt]);
                }
        }

        __syncthreads();                       // all warps done reading this buf
        if (kt + 1 < NKT) {
            if (kt + 2 < NKT) {
                ISSUE_STAGE(kt + 2); CP_COMMIT();
                CP_WAIT(1);                    // stage kt+1 complete
            } else {
                CP_WAIT(0);
            }
            __syncthreads();
        }
    }

    // ---- epilogue: sim = ACC0 + ACC1 / 2048 ----
    const float s2 = 1.0f / 2048.0f;
    const int grp = lane >> 2;
    const int tq  = lane & 3;
#pragma unroll
    for (int mt = 0; mt < 4; mt++) {
        int row0 = bm + wm + mt * 16 + grp;
        int row1 = row0 + 8;
#pragma unroll
        for (int nt = 0; nt < 4; nt++) {
            int col = bn + wn + nt * 8 + tq * 2;
            float2 lo, hi;
            lo.x = acc0[mt][nt][0] + acc1[mt][nt][0] * s2;
            lo.y = acc0[mt][nt][1] + acc1[mt][nt][1] * s2;
            hi.x = acc0[mt][nt][2] + acc1[mt][nt][2] * s2;
            hi.y = acc0[mt][nt][3] + acc1[mt][nt][3] * s2;
            *(float2*)&g_sim[(size_t)row0 * KCB + col] = lo;
            *(float2*)&g_sim[(size_t)row1 * KCB + col] = hi;
        }
    }
#undef ISSUE_STAGE
}

// ---------------- softmax / argmax / entropy / diversity --------------------
__global__ void softmax_kernel(int N, int K)
{
    __shared__ float  sdiv[KCB];
    __shared__ float  rv[256];
    __shared__ int    ri[256];
    __shared__ double dv[256];
    const int tid = threadIdx.x;

    for (int c = tid; c < K; c += 256) sdiv[c] = 0.0f;
    __syncthreads();

    double hloc = 0.0;
    const int row0 = blockIdx.x * 16;
    for (int r = 0; r < 16; r++) {
        const int row = row0 + r;
        const float* __restrict__ srow = g_sim + (size_t)row * K;

        float s[8];
#pragma unroll
        for (int j = 0; j < 8; j++) s[j] = srow[tid + 256 * j];

        float m = s[0]; int mi = tid;
#pragma unroll
        for (int j = 1; j < 8; j++) {
            int c = tid + 256 * j;
            if (s[j] > m) { m = s[j]; mi = c; }
        }
        rv[tid] = m; ri[tid] = mi;
        __syncthreads();
        for (int off = 128; off > 0; off >>= 1) {
            if (tid < off) {
                float ov = rv[tid + off]; int oi = ri[tid + off];
                if (ov > rv[tid] || (ov == rv[tid] && oi < ri[tid])) {
                    rv[tid] = ov; ri[tid] = oi;
                }
            }
            __syncthreads();
        }
        float rowmax = rv[0]; int rowidx = ri[0];
        __syncthreads();

        float e[8]; float ts = 0.0f;
#pragma unroll
        for (int j = 0; j < 8; j++) { e[j] = expf(s[j] - rowmax); ts += e[j]; }
        rv[tid] = ts;
        __syncthreads();
        for (int off = 128; off > 0; off >>= 1) {
            if (tid < off) rv[tid] += rv[tid + off];
            __syncthreads();
        }
        float dsum = rv[0];
        __syncthreads();

        float hrow = 0.0f;
#pragma unroll
        for (int j = 0; j < 8; j++) {
            float p = e[j] / dsum;
            sdiv[tid + 256 * j] += p;
            hrow += p * log2f(p + 1e-8f);
        }
        hloc += (double)hrow;

        if (tid == 0) {
            g_nn[row] = rowidx;
            atomicAdd(&g_counts[rowidx], 1.0f);
        }
    }

    __syncthreads();
    for (int c = tid; c < K; c += 256) atomicAdd(&g_div[c], sdiv[c]);

    dv[tid] = hloc;
    __syncthreads();
    for (int off = 128; off > 0; off >>= 1) {
        if (tid < off) dv[tid] += dv[tid + off];
        __syncthreads();
    }
    if (tid == 0) atomicAdd(&g_hclust, dv[0]);
}

// ---------------- loss + new_counts -----------------------------------------
__global__ void finalize_kernel(const float* __restrict__ cc,
                                const int* __restrict__ train,
                                float* __restrict__ out_counts,
                                int N, int K)
{
    __shared__ double dv[1024];
    const int tid = threadIdx.x;
    const float invN = 1.0f / (float)N;
    const int tr = train[0];

    double acc = 0.0;
    for (int c = tid; c < K; c += 1024) {
        float d = g_div[c] * invN;
        acc += (double)(d * log2f(d + 1e-8f));
        float nc = tr ? (0.99f * cc[c] + 0.01f * g_counts[c]) : cc[c];
        out_counts[c] = nc;
    }
    dv[tid] = acc;
    __syncthreads();
    for (int off = 512; off > 0; off >>= 1) {
        if (tid < off) dv[tid] += dv[tid + off];
        __syncthreads();
    }
    if (tid == 0) {
        float h_clust = -(float)(g_hclust / (double)N);
        float h_div   = -(float)dv[0];
        g_loss = h_clust - 1.0f * h_div;
    }
}

// ---------------- quantized output (warp per row) ----------------------------
__global__ void quantize_kernel(const float* __restrict__ inp,
                                const float* __restrict__ cb,
                                float* __restrict__ outq, int N, int D)
{
    const int warp = threadIdx.x >> 5;
    const int lane = threadIdx.x & 31;
    const int row = blockIdx.x * 8 + warp;
    if (row >= N) return;

    const int idx = g_nn[row];
    const float* __restrict__ q = cb + (size_t)idx * D;
    const float* __restrict__ x = inp + (size_t)row * D;
    float* __restrict__ o = outq + (size_t)row * D;

    float4 qa[4];
    float s = 0.0f;
#pragma unroll
    for (int j = 0; j < 4; j++) {
        qa[j] = *(const float4*)&q[(lane + 32 * j) * 4];
        s += qa[j].x + qa[j].y + qa[j].z + qa[j].w;
    }
#pragma unroll
    for (int off = 16; off > 0; off >>= 1) s += __shfl_xor_sync(0xffffffffu, s, off);
    const float mean = s / (float)D;

    float ss = 0.0f;
#pragma unroll
    for (int j = 0; j < 4; j++) {
        qa[j].x -= mean; qa[j].y -= mean; qa[j].z -= mean; qa[j].w -= mean;
        ss += qa[j].x*qa[j].x + qa[j].y*qa[j].y + qa[j].z*qa[j].z + qa[j].w*qa[j].w;
    }
#pragma unroll
    for (int off = 16; off > 0; off >>= 1) ss += __shfl_xor_sync(0xffffffffu, ss, off);
    const float nrm = sqrtf(ss);

#pragma unroll
    for (int j = 0; j < 4; j++) {
        float4 xi = *(const float4*)&x[(lane + 32 * j) * 4];
        float4 ov;
        ov.x = xi.x + (qa[j].x / nrm - xi.x);
        ov.y = xi.y + (qa[j].y / nrm - xi.y);
        ov.z = xi.z + (qa[j].z / nrm - xi.z);
        ov.w = xi.w + (qa[j].w / nrm - xi.w);
        *(float4*)&o[(lane + 32 * j) * 4] = ov;
    }
}

// ---------------- bulk output writers ----------------------------------------
__global__ void fill_loss_kernel(float* __restrict__ dst, size_t n4)
{
    const float v = g_loss;
    const float4 f = make_float4(v, v, v, v);
    size_t i = (size_t)blockIdx.x * blockDim.x + threadIdx.x;
    const size_t stride = (size_t)gridDim.x * blockDim.x;
    for (; i < n4; i += stride) ((float4*)dst)[i] = f;
}

__global__ void write_idx_kernel(float* __restrict__ dst, int N)
{
    int i = blockIdx.x * blockDim.x + threadIdx.x;
    if (i < N) dst[i] = (float)g_nn[i];
}

__global__ void copy_kernel(const float* __restrict__ src, float* __restrict__ dst, size_t n4)
{
    size_t i = (size_t)blockIdx.x * blockDim.x + threadIdx.x;
    const size_t stride = (size_t)gridDim.x * blockDim.x;
    for (; i < n4; i += stride) ((float4*)dst)[i] = ((const float4*)src)[i];
}

// ---------------- launch ------------------------------------------------------
extern "C" void kernel_launch(void* const* d_in, const int* in_sizes, int n_in,
                              void* d_out, int out_size)
{
    const float* inp = (const float*)d_in[0];
    const float* cb  = (const float*)d_in[1];
    const float* cc  = (const float*)d_in[2];
    const int*   trn = (const int*)d_in[3];

    const int K = in_sizes[2];            // 2048
    const int D = in_sizes[1] / K;        // 512
    const int N = in_sizes[0] / D;        // 16384

    float* out = (float*)d_out;
    const size_t qN    = (size_t)N * D;
    const size_t lossN = (size_t)N * K;
    float* out_q    = out;
    float* out_loss = out + qN;
    float* out_idx  = out + qN + lossN;
    float* out_cb   = out + qN + lossN + (size_t)N;
    float* out_cnt  = out + qN + lossN + (size_t)N + (size_t)K * D;

    cudaFuncSetAttribute(gemm_hmma_kernel,
                         cudaFuncAttributeMaxDynamicSharedMemorySize, GEMM_SMEM);

    zero_kernel<<<1, 256>>>(K);

    // split fp32 -> 2x fp16 planes
    {
        int na4 = N * D / 4;
        int nb4 = K * D / 4;
        split_a_kernel<<<(na4 + 255) / 256, 256>>>(inp, na4);
        split_b_kernel<<<(nb4 + 255) / 256, 256>>>(cb, nb4);
    }

    dim3 ggrid(K / BNT, N / BMT);   // (16, 128)
    gemm_hmma_kernel<<<ggrid, 256, GEMM_SMEM>>>();

    softmax_kernel<<<N / 16, 256>>>(N, K);
    finalize_kernel<<<1, 1024>>>(cc, trn, out_cnt, N, K);

    quantize_kernel<<<N / 8, 256>>>(inp, cb, out_q, N, D);
    fill_loss_kernel<<<4096, 256>>>(out_loss, lossN / 4);
    write_idx_kernel<<<(N + 255) / 256, 256>>>(out_idx, N);
    copy_kernel<<<2048, 256>>>(cb, out_cb, (size_t)K * D / 4);
}

// round 12
// speedup vs baseline: 1.5628x; 1.1288x over previous
#include <cuda_runtime.h>
#include <cuda_fp16.h>
#include <cstdint>
#include <math.h>

// Problem constants (fixed shapes for this problem)
#define NMAX 16384
#define KCB  2048
#define DDIM 512

// ---------------- device scratch (no allocations allowed) ----------------
__device__ float  g_sim[(size_t)NMAX * KCB];   // similarity matrix [N, K]
__device__ float  g_div[KCB];
__device__ float  g_counts[KCB];
__device__ int    g_nn[NMAX];
__device__ double g_hclust;
__device__ float  g_loss;

// fp16 2-way split planes (a2 unscaled; b2 scaled by 2048)
__device__ __half g_A1[(size_t)NMAX * DDIM];
__device__ __half g_A2[(size_t)NMAX * DDIM];
__device__ __half g_B1[(size_t)KCB * DDIM];
__device__ __half g_B2[(size_t)KCB * DDIM];

// ---------------- PTX helpers ------------------------------------------------
__device__ __forceinline__ uint32_t smem_to_u32(const void* smem_ptr) {
    uint32_t addr;
    asm("{ .reg .u64 tmp; cvta.to.shared.u64 tmp, %1; cvt.u32.u64 %0, tmp; }"
        : "=r"(addr) : "l"(smem_ptr));
    return addr;
}
__device__ __forceinline__ void cp_async16(uint32_t dst, const void* src) {
    asm volatile("cp.async.cg.shared.global [%0], [%1], 16;\n"
                 :: "r"(dst), "l"(src));
}
#define CP_COMMIT() asm volatile("cp.async.commit_group;\n" ::: "memory")
#define CP_WAIT(n)  asm volatile("cp.async.wait_group %0;\n" :: "n"(n) : "memory")

__device__ __forceinline__ void ldsm_x4(uint32_t* r, uint32_t addr) {
    asm volatile("ldmatrix.sync.aligned.m8n8.x4.shared.b16 {%0,%1,%2,%3}, [%4];"
                 : "=r"(r[0]), "=r"(r[1]), "=r"(r[2]), "=r"(r[3]) : "r"(addr));
}
#define MMA16816(d, a, b) \
    asm volatile("mma.sync.aligned.m16n8k16.row.col.f32.f16.f16.f32 " \
        "{%0,%1,%2,%3}, {%4,%5,%6,%7}, {%8,%9}, {%0,%1,%2,%3};" \
        : "+f"((d)[0]), "+f"((d)[1]), "+f"((d)[2]), "+f"((d)[3]) \
        : "r"((a)[0]), "r"((a)[1]), "r"((a)[2]), "r"((a)[3]), \
          "r"((b)[0]), "r"((b)[1]))

// ---------------- zero accumulators -----------------------------------------
__global__ void zero_kernel(int K) {
    int t = blockIdx.x * blockDim.x + threadIdx.x;
    for (int c = t; c < K; c += blockDim.x * gridDim.x) {
        g_div[c] = 0.0f;
        g_counts[c] = 0.0f;
    }
    if (t == 0) g_hclust = 0.0;
}

// ---------------- fp32 -> 2x fp16 split -------------------------------------
__global__ void split_a_kernel(const float* __restrict__ x, int n4)
{
    int i = blockIdx.x * blockDim.x + threadIdx.x;
    if (i >= n4) return;
    float4 v = ((const float4*)x)[i];
    float f[4] = { v.x, v.y, v.z, v.w };
    union P { __half h[4]; uint2 u; } p1, p2;
#pragma unroll
    for (int j = 0; j < 4; j++) {
        __half a = __float2half_rn(f[j]);
        p1.h[j] = a;
        p2.h[j] = __float2half_rn(f[j] - __half2float(a));  // unscaled residual
    }
    ((uint2*)g_A1)[i] = p1.u;
    ((uint2*)g_A2)[i] = p2.u;
}
__global__ void split_b_kernel(const float* __restrict__ x, int n4)
{
    int i = blockIdx.x * blockDim.x + threadIdx.x;
    if (i >= n4) return;
    float4 v = ((const float4*)x)[i];
    float f[4] = { v.x, v.y, v.z, v.w };
    union P { __half h[4]; uint2 u; } p1, p2;
#pragma unroll
    for (int j = 0; j < 4; j++) {
        __half a = __float2half_rn(f[j]);
        p1.h[j] = a;
        p2.h[j] = __float2half_rn((f[j] - __half2float(a)) * 2048.0f);  // scaled
    }
    ((uint2*)g_B1)[i] = p1.u;
    ((uint2*)g_B2)[i] = p2.u;
}

// ---------------- HMMA GEMM: g_sim = A[M,D] * B[K,D]^T ----------------------
// CTA tile 128x128, BK=32, 4-stage cp.async pipeline, ONE sync per k-iter.
// 8 warps (2M x 4N), warp tile 64x32.
// Split products: ACC0 += a1*b1 + a2*b1 ; ACC1 += a1*b2 ; sim = ACC0+ACC1/2048.
#define BMT 128
#define BNT 128
#define BKT 32
#define NSTAGE 4
#define STAGE_B 32768           // 4 tiles x (128*32*2B)
#define TOFF_A1 0
#define TOFF_A2 8192
#define TOFF_B1 16384
#define TOFF_B2 24576
#define GEMM_SMEM (NSTAGE * STAGE_B) // 131072

__global__ __launch_bounds__(256, 1) void gemm_hmma_kernel()
{
    extern __shared__ __align__(128) char smem[];
    const uint32_t sbase = smem_to_u32(smem);
    const int tid  = threadIdx.x;
    const int lane = tid & 31;
    const int wid  = tid >> 5;
    const int bn = blockIdx.x * BNT;
    const int bm = blockIdx.y * BMT;

    const __half* gA1 = g_A1 + (size_t)bm * DDIM;
    const __half* gA2 = g_A2 + (size_t)bm * DDIM;
    const __half* gB1 = g_B1 + (size_t)bn * DDIM;
    const __half* gB2 = g_B2 + (size_t)bn * DDIM;

    // per-thread load slots: 2 x 16B per tile (512 chunks / 256 threads)
    const int q0 = tid, q1 = tid + 256;
    const int r0 = q0 >> 2, c0 = q0 & 3;
    const int r1 = q1 >> 2, c1 = q1 & 3;
    const uint32_t so0 = (uint32_t)(r0 * 64 + ((c0 ^ (r0 & 3)) << 4));
    const uint32_t so1 = (uint32_t)(r1 * 64 + ((c1 ^ (r1 & 3)) << 4));
    const size_t go0 = (size_t)r0 * DDIM + c0 * 8;
    const size_t go1 = (size_t)r1 * DDIM + c1 * 8;

    // compute mapping: warp (wm, wn), 4 m16 tiles x 4 n8 tiles
    const int wm = (wid >> 2) * 64;
    const int wn = (wid & 3) * 32;

    float acc0[4][4][4];
    float acc1[4][4][4];
#pragma unroll
    for (int i = 0; i < 4; i++)
#pragma unroll
        for (int j = 0; j < 4; j++)
#pragma unroll
            for (int k = 0; k < 4; k++) { acc0[i][j][k] = 0.0f; acc1[i][j][k] = 0.0f; }

    const int NKT = DDIM / BKT;  // 16

#define ISSUE_STAGE(kt) do { \
    uint32_t sb_ = sbase + (uint32_t)((kt) % NSTAGE) * STAGE_B; \
    size_t ko_ = (size_t)(kt) * BKT; \
    cp_async16(sb_ + TOFF_A1 + so0, gA1 + go0 + ko_); \
    cp_async16(sb_ + TOFF_A1 + so1, gA1 + go1 + ko_); \
    cp_async16(sb_ + TOFF_A2 + so0, gA2 + go0 + ko_); \
    cp_async16(sb_ + TOFF_A2 + so1, gA2 + go1 + ko_); \
    cp_async16(sb_ + TOFF_B1 + so0, gB1 + go0 + ko_); \
    cp_async16(sb_ + TOFF_B1 + so1, gB1 + go1 + ko_); \
    cp_async16(sb_ + TOFF_B2 + so0, gB2 + go0 + ko_); \
    cp_async16(sb_ + TOFF_B2 + so1, gB2 + go1 + ko_); \
} while (0)

    // prologue: stages 0..NSTAGE-2 in flight
    ISSUE_STAGE(0); CP_COMMIT();
    ISSUE_STAGE(1); CP_COMMIT();
    ISSUE_STAGE(2); CP_COMMIT();

    // ldmatrix lane-address components (same pattern for A and B operands)
    const int f_lr = lane & 15;          // row within 16-row tile
    const int f_hi = lane >> 4;          // k-chunk select (0/1)

    for (int kt = 0; kt < NKT; kt++) {
        CP_WAIT(NSTAGE - 2);             // this thread's stage kt copies done
        __syncthreads();                 // everyone's copies visible; compute kt-1 fully retired
        if (kt + NSTAGE - 1 < NKT) ISSUE_STAGE(kt + NSTAGE - 1);
        CP_COMMIT();                     // always commit (empty groups keep the count honest)

        const uint32_t sb = sbase + (uint32_t)(kt % NSTAGE) * STAGE_B;

#pragma unroll
        for (int kc = 0; kc < 2; kc++) {
            // ---- A fragments (both planes) ----
            uint32_t a1f[4][4], a2f[4][4];
#pragma unroll
            for (int mt = 0; mt < 4; mt++) {
                int r = wm + mt * 16 + f_lr;
                int c = kc * 2 + f_hi;
                uint32_t ad = sb + (uint32_t)(r * 64 + ((c ^ (r & 3)) << 4));
                ldsm_x4(a1f[mt], ad + TOFF_A1);
                ldsm_x4(a2f[mt], ad + TOFF_A2);
            }
            // ---- B fragments (both planes), PLAIN ldmatrix on [n][k] tile ----
            uint32_t b1f[4][2], b2f[4][2];
#pragma unroll
            for (int nt2 = 0; nt2 < 2; nt2++) {
                int r = wn + nt2 * 16 + f_lr;
                int c = kc * 2 + f_hi;
                uint32_t bd = sb + (uint32_t)(r * 64 + ((c ^ (r & 3)) << 4));
                uint32_t m[4];
                ldsm_x4(m, bd + TOFF_B1);
                b1f[nt2*2+0][0] = m[0]; b1f[nt2*2+0][1] = m[2];
                b1f[nt2*2+1][0] = m[1]; b1f[nt2*2+1][1] = m[3];
                ldsm_x4(m, bd + TOFF_B2);
                b2f[nt2*2+0][0] = m[0]; b2f[nt2*2+0][1] = m[2];
                b2f[nt2*2+1][0] = m[1]; b2f[nt2*2+1][1] = m[3];
            }
            // ---- 48 mma ----
#pragma unroll
            for (int mt = 0; mt < 4; mt++)
#pragma unroll
                for (int nt = 0; nt < 4; nt++) {
                    MMA16816(acc0[mt][nt], a1f[mt], b1f[nt]);
                    MMA16816(acc0[mt][nt], a2f[mt], b1f[nt]);
                    MMA16816(acc1[mt][nt], a1f[mt], b2f[nt]);
                }
        }
    }

    // ---- epilogue: sim = ACC0 + ACC1 / 2048 ----
    const float s2 = 1.0f / 2048.0f;
    const int grp = lane >> 2;
    const int tq  = lane & 3;
#pragma unroll
    for (int mt = 0; mt < 4; mt++) {
        int row0 = bm + wm + mt * 16 + grp;
        int row1 = row0 + 8;
#pragma unroll
        for (int nt = 0; nt < 4; nt++) {
            int col = bn + wn + nt * 8 + tq * 2;
            float2 lo, hi;
            lo.x = acc0[mt][nt][0] + acc1[mt][nt][0] * s2;
            lo.y = acc0[mt][nt][1] + acc1[mt][nt][1] * s2;
            hi.x = acc0[mt][nt][2] + acc1[mt][nt][2] * s2;
            hi.y = acc0[mt][nt][3] + acc1[mt][nt][3] * s2;
            *(float2*)&g_sim[(size_t)row0 * KCB + col] = lo;
            *(float2*)&g_sim[(size_t)row1 * KCB + col] = hi;
        }
    }
#undef ISSUE_STAGE
}

// ---------------- softmax / argmax / entropy / diversity --------------------
// Fast-math intrinsics: __expf/__log2f (abs err ~2e-7 on log2, ~5e-7 rel on exp)
// contribute < 1e-5 absolute to h_clust; argmax reads raw s, unaffected.
__global__ void softmax_kernel(int N, int K, float* __restrict__ out_idx)
{
    __shared__ float  sdiv[KCB];
    __shared__ float  rv[256];
    __shared__ int    ri[256];
    __shared__ double dv[256];
    const int tid = threadIdx.x;

    for (int c = tid; c < K; c += 256) sdiv[c] = 0.0f;
    __syncthreads();

    double hloc = 0.0;
    const int row0 = blockIdx.x * 16;
    for (int r = 0; r < 16; r++) {
        const int row = row0 + r;
        const float* __restrict__ srow = g_sim + (size_t)row * K;

        float s[8];
#pragma unroll
        for (int j = 0; j < 8; j++) s[j] = srow[tid + 256 * j];

        float m = s[0]; int mi = tid;
#pragma unroll
        for (int j = 1; j < 8; j++) {
            int c = tid + 256 * j;
            if (s[j] > m) { m = s[j]; mi = c; }
        }
        rv[tid] = m; ri[tid] = mi;
        __syncthreads();
        for (int off = 128; off > 0; off >>= 1) {
            if (tid < off) {
                float ov = rv[tid + off]; int oi = ri[tid + off];
                if (ov > rv[tid] || (ov == rv[tid] && oi < ri[tid])) {
                    rv[tid] = ov; ri[tid] = oi;
                }
            }
            __syncthreads();
        }
        float rowmax = rv[0]; int rowidx = ri[0];
        __syncthreads();

        float e[8]; float ts = 0.0f;
#pragma unroll
        for (int j = 0; j < 8; j++) { e[j] = __expf(s[j] - rowmax); ts += e[j]; }
        rv[tid] = ts;
        __syncthreads();
        for (int off = 128; off > 0; off >>= 1) {
            if (tid < off) rv[tid] += rv[tid + off];
            __syncthreads();
        }
        float dsum = rv[0];
        __syncthreads();

        float inv = 1.0f / dsum;
        float hrow = 0.0f;
#pragma unroll
        for (int j = 0; j < 8; j++) {
            float p = e[j] * inv;
            sdiv[tid + 256 * j] += p;
            hrow += p * __log2f(p + 1e-8f);
        }
        hloc += (double)hrow;

        if (tid == 0) {
            g_nn[row] = rowidx;
            out_idx[row] = (float)rowidx;
            atomicAdd(&g_counts[rowidx], 1.0f);
        }
    }

    __syncthreads();
    for (int c = tid; c < K; c += 256) atomicAdd(&g_div[c], sdiv[c]);

    dv[tid] = hloc;
    __syncthreads();
    for (int off = 128; off > 0; off >>= 1) {
        if (tid < off) dv[tid] += dv[tid + off];
        __syncthreads();
    }
    if (tid == 0) atomicAdd(&g_hclust, dv[0]);
}

// ---------------- loss + new_counts -----------------------------------------
__global__ void finalize_kernel(const float* __restrict__ cc,
                                const int* __restrict__ train,
                                float* __restrict__ out_counts,
                                int N, int K)
{
    __shared__ double dv[1024];
    const int tid = threadIdx.x;
    const float invN = 1.0f / (float)N;
    const int tr = train[0];

    double acc = 0.0;
    for (int c = tid; c < K; c += 1024) {
        float d = g_div[c] * invN;
        acc += (double)(d * log2f(d + 1e-8f));
        float nc = tr ? (0.99f * cc[c] + 0.01f * g_counts[c]) : cc[c];
        out_counts[c] = nc;
    }
    dv[tid] = acc;
    __syncthreads();
    for (int off = 512; off > 0; off >>= 1) {
        if (tid < off) dv[tid] += dv[tid + off];
        __syncthreads();
    }
    if (tid == 0) {
        float h_clust = -(float)(g_hclust / (double)N);
        float h_div   = -(float)dv[0];
        g_loss = h_clust - 1.0f * h_div;
    }
}

// ---------------- quantized output (warp per row) ----------------------------
__global__ void quantize_kernel(const float* __restrict__ inp,
                                const float* __restrict__ cb,
                                float* __restrict__ outq, int N, int D)
{
    const int warp = threadIdx.x >> 5;
    const int lane = threadIdx.x & 31;
    const int row = blockIdx.x * 8 + warp;
    if (row >= N) return;

    const int idx = g_nn[row];
    const float* __restrict__ q = cb + (size_t)idx * D;
    const float* __restrict__ x = inp + (size_t)row * D;
    float* __restrict__ o = outq + (size_t)row * D;

    float4 qa[4];
    float s = 0.0f;
#pragma unroll
    for (int j = 0; j < 4; j++) {
        qa[j] = *(const float4*)&q[(lane + 32 * j) * 4];
        s += qa[j].x + qa[j].y + qa[j].z + qa[j].w;
    }
#pragma unroll
    for (int off = 16; off > 0; off >>= 1) s += __shfl_xor_sync(0xffffffffu, s, off);
    const float mean = s / (float)D;

    float ss = 0.0f;
#pragma unroll
    for (int j = 0; j < 4; j++) {
        qa[j].x -= mean; qa[j].y -= mean; qa[j].z -= mean; qa[j].w -= mean;
        ss += qa[j].x*qa[j].x + qa[j].y*qa[j].y + qa[j].z*qa[j].z + qa[j].w*qa[j].w;
    }
#pragma unroll
    for (int off = 16; off > 0; off >>= 1) ss += __shfl_xor_sync(0xffffffffu, ss, off);
    const float nrm = sqrtf(ss);

#pragma unroll
    for (int j = 0; j < 4; j++) {
        float4 xi = *(const float4*)&x[(lane + 32 * j) * 4];
        float4 ov;
        ov.x = xi.x + (qa[j].x / nrm - xi.x);
        ov.y = xi.y + (qa[j].y / nrm - xi.y);
        ov.z = xi.z + (qa[j].z / nrm - xi.z);
        ov.w = xi.w + (qa[j].w / nrm - xi.w);
        *(float4*)&o[(lane + 32 * j) * 4] = ov;
    }
}

// ---------------- bulk output writers ----------------------------------------
__global__ void fill_loss_kernel(float* __restrict__ dst, size_t n4)
{
    const float v = g_loss;
    const float4 f = make_float4(v, v, v, v);
    size_t i = (size_t)blockIdx.x * blockDim.x + threadIdx.x;
    const size_t stride = (size_t)gridDim.x * blockDim.x;
    for (; i < n4; i += stride) ((float4*)dst)[i] = f;
}

__global__ void copy_kernel(const float* __restrict__ src, float* __restrict__ dst, size_t n4)
{
    size_t i = (size_t)blockIdx.x * blockDim.x + threadIdx.x;
    const size_t stride = (size_t)gridDim.x * blockDim.x;
    for (; i < n4; i += stride) ((float4*)dst)[i] = ((const float4*)src)[i];
}

// ---------------- launch ------------------------------------------------------
extern "C" void kernel_launch(void* const* d_in, const int* in_sizes, int n_in,
                              void* d_out, int out_size)
{
    const float* inp = (const float*)d_in[0];
    const float* cb  = (const float*)d_in[1];
    const float* cc  = (const float*)d_in[2];
    const int*   trn = (const int*)d_in[3];

    const int K = in_sizes[2];            // 2048
    const int D = in_sizes[1] / K;        // 512
    const int N = in_sizes[0] / D;        // 16384

    float* out = (float*)d_out;
    const size_t qN    = (size_t)N * D;
    const size_t lossN = (size_t)N * K;
    float* out_q    = out;
    float* out_loss = out + qN;
    float* out_idx  = out + qN + lossN;
    float* out_cb   = out + qN + lossN + (size_t)N;
    float* out_cnt  = out + qN + lossN + (size_t)N + (size_t)K * D;

    cudaFuncSetAttribute(gemm_hmma_kernel,
                         cudaFuncAttributeMaxDynamicSharedMemorySize, GEMM_SMEM);

    zero_kernel<<<1, 256>>>(K);

    // split fp32 -> 2x fp16 planes
    {
        int na4 = N * D / 4;
        int nb4 = K * D / 4;
        split_a_kernel<<<(na4 + 255) / 256, 256>>>(inp, na4);
        split_b_kernel<<<(nb4 + 255) / 256, 256>>>(cb, nb4);
    }

    dim3 ggrid(K / BNT, N / BMT);   // (16, 128)
    gemm_hmma_kernel<<<ggrid, 256, GEMM_SMEM>>>();

    softmax_kernel<<<N / 16, 256>>>(N, K, out_idx);
    finalize_kernel<<<1, 1024>>>(cc, trn, out_cnt, N, K);

    quantize_kernel<<<N / 8, 256>>>(inp, cb, out_q, N, D);
    fill_loss_kernel<<<4096, 256>>>(out_loss, lossN / 4);
    copy_kernel<<<2048, 256>>>(cb, out_cb, (size_t)K * D / 4);
}